// round 1
// baseline (speedup 1.0000x reference)
#include <cuda_runtime.h>

// ---------------------------------------------------------------------------
// STGCN block, fp32 baseline.
//  z[n,c,l,w] = sum_p sum_cin W[p*128+c,cin] * (sum_v x[n,cin,l,v]*Aw[p,v,w])
//  acc[l] = sum_{i=0..8} z[l-i];  BN(batch stats) -> relu -> +x -> relu
// ---------------------------------------------------------------------------

namespace {
constexpr int Nb   = 8;
constexpr int Cin  = 128;
constexpr int Cout = 128;
constexpr int Lt   = 2048;
constexpr int Vv   = 25;
constexpr int Pp   = 3;
constexpr float BN_EPS = 1e-5f;

constexpr int TL    = 4;          // l-positions per CTA in k1
constexpr int LW    = TL * Vv;    // 100
constexpr int USROW = 112;        // padded Us row: TL * 28 (float4-aligned)
constexpr int AWROW = 28;         // padded Aw row
constexpr int LCH   = 256;        // l-positions per CTA in k2

constexpr size_t ZSIZE = (size_t)Nb * Cout * Lt * Vv;  // 52,428,800
}

// -------- scratch (device globals; no allocation) --------
__device__ float g_Aw[Pp * Vv * Vv];           // A * edge_importance, [p][v][w]
__device__ float g_Wt[Pp * Cin * Cout];        // Wt[(p*128+cin)*128 + c] = W[(p*128+c)*128+cin]
__device__ float g_z  [ZSIZE];                 // graph-conv output
__device__ float g_acc[ZSIZE];                 // toeplitz output
__device__ float g_sum[Cout];
__device__ float g_sumsq[Cout];
__device__ float g_scale[Cout];
__device__ float g_shift[Cout];

// -------- k0: prep (Aw, W transpose-rearrange, zero stats) --------
__global__ void k0_prep(const float* __restrict__ A, const float* __restrict__ EI,
                        const float* __restrict__ W)
{
    int tid    = blockIdx.x * blockDim.x + threadIdx.x;
    int stride = gridDim.x * blockDim.x;
    for (int i = tid; i < Pp * Vv * Vv; i += stride)
        g_Aw[i] = A[i] * EI[i % (Vv * Vv)];
    for (int i = tid; i < Pp * Cin * Cout; i += stride) {
        int k = i >> 7, cc = i & 127;      // g_Wt[k][cc]
        int p = k >> 7, cin = k & 127;     // k = p*128 + cin
        g_Wt[i] = W[((p << 7) + cc) * Cin + cin];
    }
    if (tid < Cout) { g_sum[tid] = 0.f; g_sumsq[tid] = 0.f; }
}

// -------- k1: fused A-mix + partition-summed GEMM --------
// grid (Lt/TL, Nb), 512 threads, dynamic smem.
__global__ __launch_bounds__(512)
void k1_gemm(const float* __restrict__ x)
{
    extern __shared__ float sm[];
    float* Xs  = sm;                         // [128][100]  x tile, cin-major
    float* Us  = sm + Cin * LW;              // [128][112]  U = X @ Aw_p (one p at a time)
    float* AwS = Us + Cin * USROW;           // [3][25][28] padded Aw

    const int lt  = blockIdx.x;
    const int n   = blockIdx.y;
    const int l0  = lt * TL;
    const int tid = threadIdx.x;

    // phase 1: load X tile (contiguous 100 floats per cin)
    const float* xb = x + ((size_t)n * Cin) * (Lt * Vv) + (size_t)l0 * Vv;
    #pragma unroll
    for (int it = 0; it < (Cin * LW) / 512; ++it) {
        int i   = tid + it * 512;
        int cin = i / LW;
        int r   = i - cin * LW;
        Xs[i] = xb[(size_t)cin * (Lt * Vv) + r];
    }
    // load Aw into padded smem rows
    for (int i = tid; i < Pp * Vv; i += 512) {
        int p = i / Vv, v = i - p * Vv;
        #pragma unroll
        for (int w = 0; w < Vv; ++w)
            AwS[(p * Vv + v) * AWROW + w] = g_Aw[(p * Vv + v) * Vv + w];
    }
    __syncthreads();

    const int c    = tid & 127;        // output channel
    const int lsub = tid >> 7;         // 0..3
    const int warp = tid >> 5;
    const int lane = tid & 31;
    const int p2_l   = warp >> 2;                  // 0..3
    const int p2_cin = ((warp & 3) << 5) | lane;   // 0..127

    float acc[25];
    #pragma unroll
    for (int w = 0; w < 25; ++w) acc[w] = 0.f;

    for (int p = 0; p < Pp; ++p) {
        // phase 2: Us[cin][l*28+w] = sum_v Xs[cin][l*25+v] * Aw[p][v][w]
        {
            float u[25];
            #pragma unroll
            for (int w = 0; w < 25; ++w) u[w] = 0.f;
            const float* xr = Xs + p2_cin * LW + p2_l * Vv;
            const float* ab = AwS + p * Vv * AWROW;
            for (int v = 0; v < 25; ++v) {
                float xv = xr[v];
                const float4* a4 = (const float4*)(ab + v * AWROW);
                #pragma unroll
                for (int j = 0; j < 6; ++j) {
                    float4 q = a4[j];
                    u[4*j+0] += xv * q.x;
                    u[4*j+1] += xv * q.y;
                    u[4*j+2] += xv * q.z;
                    u[4*j+3] += xv * q.w;
                }
                u[24] += xv * ab[v * AWROW + 24];
            }
            float* ur = Us + p2_cin * USROW + p2_l * 28;
            float4* ur4 = (float4*)ur;
            #pragma unroll
            for (int j = 0; j < 6; ++j)
                ur4[j] = make_float4(u[4*j+0], u[4*j+1], u[4*j+2], u[4*j+3]);
            ur[24] = u[24];
        }
        __syncthreads();

        // phase 3: acc[w] += sum_k Wt[(p*128+k)][c] * Us[k][lsub*28+w]
        const float* wcol  = g_Wt + (size_t)(p * Cin) * Cout + c;
        const float* ubase = Us + lsub * 28;
        #pragma unroll 4
        for (int k = 0; k < Cin; ++k) {
            float wv = wcol[(size_t)k * Cout];
            const float4* u4 = (const float4*)(ubase + k * USROW);
            #pragma unroll
            for (int j = 0; j < 6; ++j) {
                float4 q = u4[j];
                acc[4*j+0] += wv * q.x;
                acc[4*j+1] += wv * q.y;
                acc[4*j+2] += wv * q.z;
                acc[4*j+3] += wv * q.w;
            }
            acc[24] += wv * ubase[k * USROW + 24];
        }
        __syncthreads();   // Us reused next p
    }

    float* zo = g_z + (((size_t)n * Cout + c) * Lt + (l0 + lsub)) * Vv;
    #pragma unroll
    for (int w = 0; w < 25; ++w) zo[w] = acc[w];
}

// -------- k2: 9-tap temporal sum + per-channel stats --------
// grid (Lt/LCH, Cout, Nb), 256 threads
__global__ __launch_bounds__(256)
void k2_toeplitz()
{
    __shared__ float zs[(LCH + 8) * Vv];
    __shared__ float rs[8], rss[8];
    const int lc = blockIdx.x, cch = blockIdx.y, n = blockIdx.z;
    const int l0 = lc * LCH;

    const float* zr = g_z + ((size_t)n * Cout + cch) * ((size_t)Lt * Vv);
    for (int i = threadIdx.x; i < (LCH + 8) * Vv; i += 256) {
        int l = l0 - 8 + i / Vv;
        zs[i] = (l >= 0) ? zr[(size_t)l * Vv + (i % Vv)] : 0.f;
    }
    __syncthreads();

    const int l = threadIdx.x;   // local output row
    float a[25];
    #pragma unroll
    for (int w = 0; w < 25; ++w) a[w] = zs[l * Vv + w];
    #pragma unroll
    for (int r = 1; r < 9; ++r) {
        #pragma unroll
        for (int w = 0; w < 25; ++w) a[w] += zs[(l + r) * Vv + w];
    }

    float* ao = g_acc + (((size_t)n * Cout + cch) * Lt + (l0 + l)) * Vv;
    float s = 0.f, ss = 0.f;
    #pragma unroll
    for (int w = 0; w < 25; ++w) { ao[w] = a[w]; s += a[w]; ss += a[w] * a[w]; }

    #pragma unroll
    for (int o = 16; o > 0; o >>= 1) {
        s  += __shfl_down_sync(0xffffffffu, s,  o);
        ss += __shfl_down_sync(0xffffffffu, ss, o);
    }
    if ((threadIdx.x & 31) == 0) { rs[threadIdx.x >> 5] = s; rss[threadIdx.x >> 5] = ss; }
    __syncthreads();
    if (threadIdx.x == 0) {
        float S = 0.f, SS = 0.f;
        #pragma unroll
        for (int i = 0; i < 8; ++i) { S += rs[i]; SS += rss[i]; }
        atomicAdd(&g_sum[cch], S);
        atomicAdd(&g_sumsq[cch], SS);
    }
}

// -------- k3: fold BN stats into scale/shift --------
__global__ void k3_bn(const float* __restrict__ gamma, const float* __restrict__ beta)
{
    int cc = threadIdx.x;
    const float cnt = (float)((size_t)Nb * Lt * Vv);
    float mean = g_sum[cc] / cnt;
    float var  = g_sumsq[cc] / cnt - mean * mean;
    float sc   = gamma[cc] * rsqrtf(var + BN_EPS);
    g_scale[cc] = sc;
    g_shift[cc] = beta[cc] - mean * sc;
}

// -------- k4: BN apply + relu + residual + relu (float4) --------
__global__ __launch_bounds__(256)
void k4_out(const float* __restrict__ x, float* __restrict__ out)
{
    size_t i4 = (size_t)blockIdx.x * blockDim.x + threadIdx.x;
    int cch = (int)(i4 / ((Lt * Vv) / 4)) & (Cout - 1);
    float sc = g_scale[cch], sh = g_shift[cch];
    float4 a  = ((const float4*)g_acc)[i4];
    float4 xv = ((const float4*)x)[i4];
    float4 o;
    o.x = fmaxf(fmaxf(a.x * sc + sh, 0.f) + xv.x, 0.f);
    o.y = fmaxf(fmaxf(a.y * sc + sh, 0.f) + xv.y, 0.f);
    o.z = fmaxf(fmaxf(a.z * sc + sh, 0.f) + xv.z, 0.f);
    o.w = fmaxf(fmaxf(a.w * sc + sh, 0.f) + xv.w, 0.f);
    ((float4*)out)[i4] = o;
}

// ---------------------------------------------------------------------------
extern "C" void kernel_launch(void* const* d_in, const int* in_sizes, int n_in,
                              void* d_out, int out_size)
{
    (void)in_sizes; (void)n_in; (void)out_size;
    const float* x     = (const float*)d_in[0];
    const float* A     = (const float*)d_in[1];
    const float* EI    = (const float*)d_in[2];
    const float* W     = (const float*)d_in[3];
    const float* gamma = (const float*)d_in[4];
    const float* beta  = (const float*)d_in[5];
    float* out = (float*)d_out;

    constexpr int SMEM_K1 = (Cin * LW + Cin * USROW + Pp * Vv * AWROW) * (int)sizeof(float);
    cudaFuncSetAttribute(k1_gemm, cudaFuncAttributeMaxDynamicSharedMemorySize, SMEM_K1);

    k0_prep<<<64, 256>>>(A, EI, W);
    k1_gemm<<<dim3(Lt / TL, Nb), 512, SMEM_K1>>>(x);
    k2_toeplitz<<<dim3(Lt / LCH, Cout, Nb), 256>>>();
    k3_bn<<<1, Cout>>>(gamma, beta);
    k4_out<<<(unsigned)(ZSIZE / 4 / 256), 256>>>(x, out);
}

// round 3
// speedup vs baseline: 2.0064x; 2.0064x over previous
#include <cuda_runtime.h>
#include <cstdint>

// ===========================================================================
// STGCN block via warp-level tf32 mma.sync (compute_103-safe, no tcgen05):
//   per p:  Y_p = W_p @ X   (m16n8k8 tf32, accum in regs)
//           z  += Y_p @ Aw_p  (C-frag -> A-frag via shuffles, no smem bounce)
//   then: stats of toeplitz(z) -> BN fold -> fused epilogue
// ===========================================================================

namespace {
constexpr int Nb = 8, Cin = 128, Cout = 128, Lt = 2048, Vv = 25, Pp = 3;
constexpr float BN_EPS = 1e-5f;

constexpr int TL   = 4;            // l per CTA
constexpr int NCOL = TL * 32;      // 128 (v padded to 32)
constexpr int XSTR = 136;          // X smem row stride (floats)
constexpr int WSTR = 136;          // W smem row stride
constexpr int ASTR = 36;           // Aw smem row stride

constexpr int X_OFF  = 0;                                  // floats
constexpr int W_OFF  = X_OFF + Cin * XSTR;                 // 17408
constexpr int AW_OFF = W_OFF + Cout * WSTR;                // 34816
constexpr int SM_FLT = AW_OFF + Pp * 32 * ASTR;            // 38272
constexpr int SMEM_K1 = SM_FLT * 4;                        // 153088 B

constexpr size_t ZSIZE = (size_t)Nb * Cout * Lt * Vv;
constexpr int LCH = 256;
}

__device__ float g_z[ZSIZE];
__device__ float g_sum[Cout], g_sumsq[Cout], g_scale[Cout], g_shift[Cout];

// -------------------- helpers --------------------
__device__ __forceinline__ uint32_t f2tf32(float x) {
    uint32_t u;
    asm("cvt.rna.tf32.f32 %0, %1;" : "=r"(u) : "f"(x));
    return u;
}
__device__ __forceinline__ void mma_tf32(float* d, const uint32_t* a, const uint32_t* b) {
    asm volatile("mma.sync.aligned.m16n8k8.row.col.f32.tf32.tf32.f32 "
        "{%0,%1,%2,%3}, {%4,%5,%6,%7}, {%8,%9}, {%0,%1,%2,%3};"
        : "+f"(d[0]), "+f"(d[1]), "+f"(d[2]), "+f"(d[3])
        : "r"(a[0]), "r"(a[1]), "r"(a[2]), "r"(a[3]), "r"(b[0]), "r"(b[1]));
}
// interleave k within groups of 8 so (k, k+4) are adjacent -> LDS.64 A-frag loads
__device__ __forceinline__ int kperm(int k) {
    return (k & ~7) + ((k & 3) << 1) + ((k >> 2) & 1);
}

// -------- k0: zero stats --------
__global__ void k0_prep() {
    int t = threadIdx.x;
    if (t < Cout) { g_sum[t] = 0.f; g_sumsq[t] = 0.f; }
}

// -------- k1: fused conv-GEMM + graph mix, tf32 mma.sync --------
// grid (Lt/TL=512, Nb), 512 threads (16 warps: 4 m-groups x 4 l's)
__global__ __launch_bounds__(512, 1)
void k1_gemm(const float* __restrict__ x, const float* __restrict__ A,
             const float* __restrict__ EI, const float* __restrict__ W)
{
    extern __shared__ float sm[];
    float* Xs  = sm + X_OFF;
    float* Ws  = sm + W_OFF;
    uint32_t* Xu  = (uint32_t*)Xs;
    uint32_t* Wu  = (uint32_t*)Ws;
    uint32_t* AWu = (uint32_t*)(sm + AW_OFF);

    const int tid  = threadIdx.x;
    const int wid  = tid >> 5;
    const int lane = tid & 31;
    const int n    = blockIdx.y;
    const int l0   = blockIdx.x * TL;

    const int wm = wid >> 2;        // m-group: rows wm*32..+31
    const int wl = wid & 3;         // l index: cols wl*32..+31
    const int m0 = wm * 32;
    const int n0 = wl * 32;
    const int r  = lane >> 2;       // row-in-group 0..7
    const int q  = lane & 3;        // quad col 0..3

    // ---- fill X (zero pad cols) ----
    for (int i = tid; i < Cin * XSTR; i += 512) Xu[i] = 0u;
    __syncthreads();
    {
        const float* xb = x + (size_t)n * Cin * (Lt * Vv) + (size_t)l0 * Vv;
        for (int i = tid; i < Cin * TL * Vv; i += 512) {   // 12800
            int cin = i / (TL * Vv);
            int j   = i - cin * (TL * Vv);
            int l   = j / Vv, v = j - l * Vv;
            Xu[cin * XSTR + l * 32 + v] = f2tf32(xb[(size_t)cin * (Lt * Vv) + j]);
        }
        // Aw: AWu[p][v*36 + w] = tf32(A[p,v,w] * EI[v,w]), zero padded to 32x32
        for (int i = tid; i < Pp * 32 * 32; i += 512) {
            int p = i >> 10, rem = i & 1023;
            int v = rem >> 5, w = rem & 31;
            float val = (v < Vv && w < Vv) ? A[p * Vv * Vv + v * Vv + w] * EI[v * Vv + w] : 0.f;
            AWu[p * 32 * ASTR + v * ASTR + w] = f2tf32(val);
        }
    }

    // shuffle indices for C-frag -> A-frag conversion
    const int sbase = (lane & ~3);
    const int sidx0 = sbase + (q >> 1);
    const int sidx1 = sidx0 + 2;
    const bool odd  = (q & 1);

    float zacc[2][4][4];
    #pragma unroll
    for (int mi = 0; mi < 2; ++mi)
        #pragma unroll
        for (int nj = 0; nj < 4; ++nj)
            #pragma unroll
            for (int i = 0; i < 4; ++i) zacc[mi][nj][i] = 0.f;

    for (int p = 0; p < Pp; ++p) {
        // ---- load W_p (k-interleaved columns) ----
        if (p > 0) __syncthreads();          // stage-A readers of W_{p-1} done
        {
            const float* wp = W + (size_t)p * Cout * Cin;
            for (int i = tid; i < Cout * Cin; i += 512) {
                int c = i >> 7, cin = i & 127;
                Wu[c * WSTR + kperm(cin)] = f2tf32(wp[i]);
            }
        }
        __syncthreads();

        // ---- stage A: Y = W_p @ X  (M=128, N=128, K=128) ----
        float yacc[2][4][4];
        #pragma unroll
        for (int mi = 0; mi < 2; ++mi)
            #pragma unroll
            for (int ni = 0; ni < 4; ++ni)
                #pragma unroll
                for (int i = 0; i < 4; ++i) yacc[mi][ni][i] = 0.f;

        #pragma unroll
        for (int kk = 0; kk < 16; ++kk) {
            const int k0 = kk * 8;
            uint32_t af[2][4];
            #pragma unroll
            for (int mi = 0; mi < 2; ++mi) {
                const uint32_t* w0 = Wu + (m0 + 16 * mi + r) * WSTR + k0 + 2 * q;
                uint2 lo = *(const uint2*)w0;               // (k=q, k=q+4)
                uint2 hi = *(const uint2*)(w0 + 8 * WSTR);  // rows +8
                af[mi][0] = lo.x; af[mi][1] = hi.x; af[mi][2] = lo.y; af[mi][3] = hi.y;
            }
            uint32_t bf[4][2];
            #pragma unroll
            for (int ni = 0; ni < 4; ++ni) {
                int col = n0 + 8 * ni + r;
                bf[ni][0] = Xu[(k0 + q) * XSTR + col];
                bf[ni][1] = Xu[(k0 + q + 4) * XSTR + col];
            }
            #pragma unroll
            for (int mi = 0; mi < 2; ++mi)
                #pragma unroll
                for (int ni = 0; ni < 4; ++ni)
                    mma_tf32(yacc[mi][ni], af[mi], bf[ni]);
        }

        // ---- convert Y C-frags -> mix A-frags (shuffles), then mix MMA ----
        // mix: z[c, w] += sum_v Y[c, v] * Aw_p[v, w]; k-frag kf == stage-A n-frag
        uint32_t amix[2][4][4];
        #pragma unroll
        for (int mi = 0; mi < 2; ++mi) {
            #pragma unroll
            for (int kf = 0; kf < 4; ++kf) {
                float c0 = yacc[mi][kf][0], c1 = yacc[mi][kf][1];
                float c2 = yacc[mi][kf][2], c3 = yacc[mi][kf][3];
                float t00 = __shfl_sync(0xffffffffu, c0, sidx0);
                float t01 = __shfl_sync(0xffffffffu, c1, sidx0);
                float t20 = __shfl_sync(0xffffffffu, c0, sidx1);
                float t21 = __shfl_sync(0xffffffffu, c1, sidx1);
                float t10 = __shfl_sync(0xffffffffu, c2, sidx0);
                float t11 = __shfl_sync(0xffffffffu, c3, sidx0);
                float t30 = __shfl_sync(0xffffffffu, c2, sidx1);
                float t31 = __shfl_sync(0xffffffffu, c3, sidx1);
                amix[mi][kf][0] = f2tf32(odd ? t01 : t00);
                amix[mi][kf][1] = f2tf32(odd ? t11 : t10);
                amix[mi][kf][2] = f2tf32(odd ? t21 : t20);
                amix[mi][kf][3] = f2tf32(odd ? t31 : t30);
            }
        }
        const uint32_t* awp = AWu + p * 32 * ASTR;
        #pragma unroll
        for (int kf = 0; kf < 4; ++kf) {
            uint32_t bf[4][2];
            #pragma unroll
            for (int nj = 0; nj < 4; ++nj) {
                int col = 8 * nj + r;
                bf[nj][0] = awp[(8 * kf + q) * ASTR + col];
                bf[nj][1] = awp[(8 * kf + q + 4) * ASTR + col];
            }
            #pragma unroll
            for (int mi = 0; mi < 2; ++mi)
                #pragma unroll
                for (int nj = 0; nj < 4; ++nj)
                    mma_tf32(zacc[mi][nj], amix[mi][kf], bf[nj]);
        }
    }

    // ---- store z fragments ----
    const int lglob = l0 + wl;
    #pragma unroll
    for (int mi = 0; mi < 2; ++mi) {
        #pragma unroll
        for (int nj = 0; nj < 4; ++nj) {
            int c_lo = m0 + 16 * mi + r;
            int w0c  = 8 * nj + 2 * q;
            float* z0 = g_z + ((size_t)(n * Cout + c_lo) * Lt + lglob) * Vv;
            float* z1 = g_z + ((size_t)(n * Cout + c_lo + 8) * Lt + lglob) * Vv;
            if (w0c < Vv)     { z0[w0c]     = zacc[mi][nj][0]; z1[w0c]     = zacc[mi][nj][2]; }
            if (w0c + 1 < Vv) { z0[w0c + 1] = zacc[mi][nj][1]; z1[w0c + 1] = zacc[mi][nj][3]; }
        }
    }
}

// -------- k2: stats of toeplitz(z) (acc never materialized) --------
__global__ __launch_bounds__(256)
void k2_stats()
{
    __shared__ float zs[(LCH + 8) * Vv];
    __shared__ float rs[8], rss[8];
    const int lc = blockIdx.x, c = blockIdx.y, n = blockIdx.z;
    const int l0 = lc * LCH;

    const float* zr = g_z + ((size_t)n * Cout + c) * ((size_t)Lt * Vv);
    for (int i = threadIdx.x; i < (LCH + 8) * Vv; i += 256) {
        int l = l0 - 8 + i / Vv;
        zs[i] = (l >= 0) ? zr[(size_t)l * Vv + (i % Vv)] : 0.f;
    }
    __syncthreads();

    const int l = threadIdx.x;
    float s = 0.f, ss = 0.f;
    #pragma unroll
    for (int w = 0; w < Vv; ++w) {
        float a = zs[l * Vv + w];
        #pragma unroll
        for (int t = 1; t < 9; ++t) a += zs[(l + t) * Vv + w];
        s += a; ss += a * a;
    }
    #pragma unroll
    for (int o = 16; o > 0; o >>= 1) {
        s  += __shfl_down_sync(0xffffffffu, s,  o);
        ss += __shfl_down_sync(0xffffffffu, ss, o);
    }
    if ((threadIdx.x & 31) == 0) { rs[threadIdx.x >> 5] = s; rss[threadIdx.x >> 5] = ss; }
    __syncthreads();
    if (threadIdx.x == 0) {
        float S = 0.f, SS = 0.f;
        #pragma unroll
        for (int i = 0; i < 8; ++i) { S += rs[i]; SS += rss[i]; }
        atomicAdd(&g_sum[c], S);
        atomicAdd(&g_sumsq[c], SS);
    }
}

// -------- k3: fold BN stats --------
__global__ void k3_bn(const float* __restrict__ gamma, const float* __restrict__ beta)
{
    int c = threadIdx.x;
    const float cnt = (float)((size_t)Nb * Lt * Vv);
    float mean = g_sum[c] / cnt;
    float var  = g_sumsq[c] / cnt - mean * mean;
    float sc   = gamma[c] * rsqrtf(var + BN_EPS);
    g_scale[c] = sc;
    g_shift[c] = beta[c] - mean * sc;
}

// -------- k4: toeplitz recompute + BN + relu + residual + relu --------
__global__ __launch_bounds__(256)
void k4_out(const float* __restrict__ x, float* __restrict__ out)
{
    __shared__ float zs[(LCH + 8) * Vv];
    const int lc = blockIdx.x, c = blockIdx.y, n = blockIdx.z;
    const int l0 = lc * LCH;

    const float* zr = g_z + ((size_t)n * Cout + c) * ((size_t)Lt * Vv);
    for (int i = threadIdx.x; i < (LCH + 8) * Vv; i += 256) {
        int l = l0 - 8 + i / Vv;
        zs[i] = (l >= 0) ? zr[(size_t)l * Vv + (i % Vv)] : 0.f;
    }
    __syncthreads();

    const int l = threadIdx.x;
    const float sc = g_scale[c], sh = g_shift[c];
    const size_t base = ((size_t)(n * Cout + c) * Lt + (l0 + l)) * Vv;
    const float* xr = x + base;
    float* orow = out + base;
    #pragma unroll
    for (int w = 0; w < Vv; ++w) {
        float a = zs[l * Vv + w];
        #pragma unroll
        for (int t = 1; t < 9; ++t) a += zs[(l + t) * Vv + w];
        orow[w] = fmaxf(fmaxf(a * sc + sh, 0.f) + xr[w], 0.f);
    }
}

// ---------------------------------------------------------------------------
extern "C" void kernel_launch(void* const* d_in, const int* in_sizes, int n_in,
                              void* d_out, int out_size)
{
    (void)in_sizes; (void)n_in; (void)out_size;
    const float* x     = (const float*)d_in[0];
    const float* A     = (const float*)d_in[1];
    const float* EI    = (const float*)d_in[2];
    const float* W     = (const float*)d_in[3];
    const float* gamma = (const float*)d_in[4];
    const float* beta  = (const float*)d_in[5];
    float* out = (float*)d_out;

    cudaFuncSetAttribute(k1_gemm, cudaFuncAttributeMaxDynamicSharedMemorySize, SMEM_K1);

    k0_prep<<<1, 128>>>();
    k1_gemm<<<dim3(Lt / TL, Nb), 512, SMEM_K1>>>(x, A, EI, W);
    k2_stats<<<dim3(Lt / LCH, Cout, Nb), 256>>>();
    k3_bn<<<1, Cout>>>(gamma, beta);
    k4_out<<<dim3(Lt / LCH, Cout, Nb), 256>>>(x, out);
}

// round 4
// speedup vs baseline: 2.1123x; 1.0527x over previous
#include <cuda_runtime.h>
#include <cstdint>

// ===========================================================================
// STGCN block via warp-level tf32 mma.sync:
//   per p:  Y_p = W_p @ X   (m16n8k8 tf32, accum in regs; W double-buffered
//                            via cp.async, X/Aw K-major for LDS.64 frags)
//           z  += Y_p @ Aw_p  (C-frag -> A-frag via shuffles, no smem bounce)
//   then: stats of toeplitz(z) -> BN fold -> fused epilogue
// ===========================================================================

namespace {
constexpr int Nb = 8, Cin = 128, Cout = 128, Lt = 2048, Vv = 25, Pp = 3;
constexpr float BN_EPS = 1e-5f;

constexpr int TL   = 4;            // l per CTA
constexpr int XSTR = 136;          // X smem row stride (floats) [row = n-col]
constexpr int WSTR = 136;          // W smem row stride
constexpr int ASTR = 36;           // Aw smem row stride

constexpr int X_OFF   = 0;                              // floats
constexpr int W0_OFF  = X_OFF + 128 * XSTR;             // 17408
constexpr int W1_OFF  = W0_OFF + Cout * WSTR;           // 34816
constexpr int AW_OFF  = W1_OFF + Cout * WSTR;           // 52224
constexpr int SM_FLT  = AW_OFF + Pp * 32 * ASTR;        // 55680
constexpr int SMEM_K1 = SM_FLT * 4;                     // 222720 B

constexpr size_t ZSIZE = (size_t)Nb * Cout * Lt * Vv;
constexpr int LCH = 256;
}

__device__ float g_z[ZSIZE];
__device__ float g_sum[Cout], g_sumsq[Cout], g_scale[Cout], g_shift[Cout];

// -------------------- helpers --------------------
__device__ __forceinline__ uint32_t f2tf32(float x) {
    uint32_t u;
    asm("cvt.rna.tf32.f32 %0, %1;" : "=r"(u) : "f"(x));
    return u;
}
__device__ __forceinline__ uint32_t smem_u32(const void* p) {
    uint32_t a;
    asm("{ .reg .u64 t; cvta.to.shared.u64 t, %1; cvt.u32.u64 %0, t; }" : "=r"(a) : "l"(p));
    return a;
}
__device__ __forceinline__ void mma_tf32(float* d, const uint32_t* a, const uint32_t* b) {
    asm volatile("mma.sync.aligned.m16n8k8.row.col.f32.tf32.tf32.f32 "
        "{%0,%1,%2,%3}, {%4,%5,%6,%7}, {%8,%9}, {%0,%1,%2,%3};"
        : "+f"(d[0]), "+f"(d[1]), "+f"(d[2]), "+f"(d[3])
        : "r"(a[0]), "r"(a[1]), "r"(a[2]), "r"(a[3]), "r"(b[0]), "r"(b[1]));
}
// interleave k within groups of 8 so (k, k+4) are word-adjacent -> LDS.64 frags
__device__ __forceinline__ int kperm(int k) {
    return (k & ~7) + ((k & 3) << 1) + ((k >> 2) & 1);
}
#define CP_COMMIT() asm volatile("cp.async.commit_group;" ::: "memory")
#define CP_WAIT(n)  asm volatile("cp.async.wait_group %0;" :: "n"(n) : "memory")

// cp.async W_p tile into smem buffer (raw fp32; tf32 mma truncates in HW)
__device__ __forceinline__ void cp_w(uint32_t wb, const float* __restrict__ wp, int tid) {
    for (int i = tid; i < Cout * Cin; i += 512) {
        int c = i >> 7, cin = i & 127;
        uint32_t dst = wb + (uint32_t)(c * WSTR + kperm(cin)) * 4u;
        asm volatile("cp.async.ca.shared.global [%0], [%1], 4;"
                     :: "r"(dst), "l"(wp + i) : "memory");
    }
}

// -------- k0: zero stats --------
__global__ void k0_prep() {
    int t = threadIdx.x;
    if (t < Cout) { g_sum[t] = 0.f; g_sumsq[t] = 0.f; }
}
// -------- dummy: shifts the ncu sampled-launch slot onto k1/k2 --------
__global__ void kdummy() {}

// -------- k1: fused conv-GEMM + graph mix, tf32 mma.sync --------
// grid (Lt/TL=512, Nb), 512 threads (16 warps: 4 m-groups x 4 l's)
__global__ __launch_bounds__(512, 1)
void k1_gemm(const float* __restrict__ x, const float* __restrict__ A,
             const float* __restrict__ EI, const float* __restrict__ W)
{
    extern __shared__ float sm[];
    uint32_t* Xu  = (uint32_t*)(sm + X_OFF);
    uint32_t* AWu = (uint32_t*)(sm + AW_OFF);

    const int tid  = threadIdx.x;
    const int wid  = tid >> 5;
    const int lane = tid & 31;
    const int n    = blockIdx.y;
    const int l0   = blockIdx.x * TL;

    const int wm = wid >> 2;        // m-group: rows wm*32..+31
    const int wl = wid & 3;         // l index: cols wl*32..+31
    const int m0 = wm * 32;
    const int n0 = wl * 32;
    const int r  = lane >> 2;       // row-in-group 0..7
    const int q  = lane & 3;        // quad col 0..3

    const uint32_t smb = smem_u32(sm);
    const uint32_t wb0 = smb + W0_OFF * 4u;
    const uint32_t wb1 = smb + W1_OFF * 4u;

    // prefetch W0, W1 (async, overlapped with X/Aw fill)
    cp_w(wb0, W, tid);                       CP_COMMIT();
    cp_w(wb1, W + Cout * Cin, tid);          CP_COMMIT();

    // ---- X tile, K-major: Xu[(l*32+v)*XSTR + kperm(cin)] ----
    {
        const float* xb = x + (size_t)n * Cin * (Lt * Vv) + (size_t)l0 * Vv;
        for (int i = tid; i < Cin * TL * Vv; i += 512) {   // 12800
            int cin = i / (TL * Vv);
            int j   = i - cin * (TL * Vv);
            int l   = j / Vv, v = j - l * Vv;
            Xu[(l * 32 + v) * XSTR + kperm(cin)] = f2tf32(xb[(size_t)cin * (Lt * Vv) + j]);
        }
        // zero padded v-columns (v=25..31) so Y pad lanes are finite
        for (int i = tid; i < TL * 7 * XSTR; i += 512) {
            int l = i / (7 * XSTR), rem = i - l * (7 * XSTR);
            int v = 25 + rem / XSTR, wd = rem % XSTR;
            Xu[(l * 32 + v) * XSTR + wd] = 0u;
        }
        // Aw K-major: AWu[p][w*ASTR + kperm(v)] = tf32(A[p,v,w]*EI[v,w]); pad=0
        for (int i = tid; i < Pp * 32 * 32; i += 512) {
            int p = i >> 10, rem = i & 1023;
            int w = rem >> 5, v = rem & 31;
            float val = (v < Vv && w < Vv) ? A[p * Vv * Vv + v * Vv + w] * EI[v * Vv + w] : 0.f;
            AWu[p * 32 * ASTR + w * ASTR + kperm(v)] = f2tf32(val);
        }
    }
    CP_WAIT(1);              // W0 resident
    __syncthreads();

    // shuffle indices for C-frag -> A-frag conversion
    const int sidx0 = (lane & ~3) + (q >> 1);
    const int sidx1 = sidx0 + 2;
    const bool odd  = (q & 1);

    float zacc[2][4][4];
    #pragma unroll
    for (int mi = 0; mi < 2; ++mi)
        #pragma unroll
        for (int nj = 0; nj < 4; ++nj)
            #pragma unroll
            for (int i = 0; i < 4; ++i) zacc[mi][nj][i] = 0.f;

    #pragma unroll
    for (int p = 0; p < Pp; ++p) {
        const uint32_t* Wu = (const uint32_t*)(sm + ((p & 1) ? W1_OFF : W0_OFF));

        // ---- stage A: Y = W_p @ X  (M=128, N=128, K=128) ----
        float yacc[2][4][4];
        #pragma unroll
        for (int mi = 0; mi < 2; ++mi)
            #pragma unroll
            for (int ni = 0; ni < 4; ++ni)
                #pragma unroll
                for (int i = 0; i < 4; ++i) yacc[mi][ni][i] = 0.f;

        #pragma unroll
        for (int kk = 0; kk < 16; ++kk) {
            const int k0 = kk * 8;
            uint32_t af[2][4];
            #pragma unroll
            for (int mi = 0; mi < 2; ++mi) {
                const uint32_t* w0 = Wu + (m0 + 16 * mi + r) * WSTR + k0 + 2 * q;
                uint2 lo = *(const uint2*)w0;
                uint2 hi = *(const uint2*)(w0 + 8 * WSTR);
                af[mi][0] = lo.x; af[mi][1] = hi.x; af[mi][2] = lo.y; af[mi][3] = hi.y;
            }
            uint32_t bf[4][2];
            #pragma unroll
            for (int ni = 0; ni < 4; ++ni) {
                uint2 b = *(const uint2*)(Xu + (n0 + 8 * ni + r) * XSTR + k0 + 2 * q);
                bf[ni][0] = b.x; bf[ni][1] = b.y;
            }
            #pragma unroll
            for (int mi = 0; mi < 2; ++mi)
                #pragma unroll
                for (int ni = 0; ni < 4; ++ni)
                    mma_tf32(yacc[mi][ni], af[mi], bf[ni]);
        }

        // ---- convert Y C-frags -> mix A-frags (shuffles), then mix MMA ----
        uint32_t amix[2][4][4];
        #pragma unroll
        for (int mi = 0; mi < 2; ++mi) {
            #pragma unroll
            for (int kf = 0; kf < 4; ++kf) {
                float c0 = yacc[mi][kf][0], c1 = yacc[mi][kf][1];
                float c2 = yacc[mi][kf][2], c3 = yacc[mi][kf][3];
                float t00 = __shfl_sync(0xffffffffu, c0, sidx0);
                float t01 = __shfl_sync(0xffffffffu, c1, sidx0);
                float t20 = __shfl_sync(0xffffffffu, c0, sidx1);
                float t21 = __shfl_sync(0xffffffffu, c1, sidx1);
                float t10 = __shfl_sync(0xffffffffu, c2, sidx0);
                float t11 = __shfl_sync(0xffffffffu, c3, sidx0);
                float t30 = __shfl_sync(0xffffffffu, c2, sidx1);
                float t31 = __shfl_sync(0xffffffffu, c3, sidx1);
                amix[mi][kf][0] = f2tf32(odd ? t01 : t00);
                amix[mi][kf][1] = f2tf32(odd ? t11 : t10);
                amix[mi][kf][2] = f2tf32(odd ? t21 : t20);
                amix[mi][kf][3] = f2tf32(odd ? t31 : t30);
            }
        }
        const uint32_t* awp = AWu + p * 32 * ASTR;
        #pragma unroll
        for (int kf = 0; kf < 4; ++kf) {
            uint32_t bfm[4][2];
            #pragma unroll
            for (int nj = 0; nj < 4; ++nj) {
                uint2 b = *(const uint2*)(awp + (8 * nj + r) * ASTR + 8 * kf + 2 * q);
                bfm[nj][0] = b.x; bfm[nj][1] = b.y;
            }
            #pragma unroll
            for (int mi = 0; mi < 2; ++mi)
                #pragma unroll
                for (int nj = 0; nj < 4; ++nj)
                    mma_tf32(zacc[mi][nj], amix[mi][kf], bfm[nj]);
        }

        // pipeline: after p=0 reads of buf0 complete, stream W2 into buf0
        if (p == 0) {
            __syncthreads();                        // all reads of buf0 done
            cp_w(wb0, W + 2 * Cout * Cin, tid);     CP_COMMIT();
            CP_WAIT(1);                             // W1 resident
            __syncthreads();
        } else if (p == 1) {
            CP_WAIT(0);                             // W2 resident
            __syncthreads();
        }
    }

    // ---- store z fragments ----
    const int lglob = l0 + wl;
    #pragma unroll
    for (int mi = 0; mi < 2; ++mi) {
        #pragma unroll
        for (int nj = 0; nj < 4; ++nj) {
            int c_lo = m0 + 16 * mi + r;
            int w0c  = 8 * nj + 2 * q;
            float* z0 = g_z + ((size_t)(n * Cout + c_lo) * Lt + lglob) * Vv;
            float* z1 = g_z + ((size_t)(n * Cout + c_lo + 8) * Lt + lglob) * Vv;
            if (w0c < Vv)     { z0[w0c]     = zacc[mi][nj][0]; z1[w0c]     = zacc[mi][nj][2]; }
            if (w0c + 1 < Vv) { z0[w0c + 1] = zacc[mi][nj][1]; z1[w0c + 1] = zacc[mi][nj][3]; }
        }
    }
}

// -------- k2: stats of toeplitz(z) (acc never materialized) --------
__global__ __launch_bounds__(256)
void k2_stats()
{
    __shared__ float zs[(LCH + 8) * Vv];
    __shared__ float rs[8], rss[8];
    const int lc = blockIdx.x, c = blockIdx.y, n = blockIdx.z;
    const int l0 = lc * LCH;

    const float* zr = g_z + ((size_t)n * Cout + c) * ((size_t)Lt * Vv);
    for (int i = threadIdx.x; i < (LCH + 8) * Vv; i += 256) {
        int l = l0 - 8 + i / Vv;
        zs[i] = (l >= 0) ? zr[(size_t)l * Vv + (i % Vv)] : 0.f;
    }
    __syncthreads();

    const int l = threadIdx.x;
    float s = 0.f, ss = 0.f;
    #pragma unroll
    for (int w = 0; w < Vv; ++w) {
        float a = zs[l * Vv + w];
        #pragma unroll
        for (int t = 1; t < 9; ++t) a += zs[(l + t) * Vv + w];
        s += a; ss += a * a;
    }
    #pragma unroll
    for (int o = 16; o > 0; o >>= 1) {
        s  += __shfl_down_sync(0xffffffffu, s,  o);
        ss += __shfl_down_sync(0xffffffffu, ss, o);
    }
    if ((threadIdx.x & 31) == 0) { rs[threadIdx.x >> 5] = s; rss[threadIdx.x >> 5] = ss; }
    __syncthreads();
    if (threadIdx.x == 0) {
        float S = 0.f, SS = 0.f;
        #pragma unroll
        for (int i = 0; i < 8; ++i) { S += rs[i]; SS += rss[i]; }
        atomicAdd(&g_sum[c], S);
        atomicAdd(&g_sumsq[c], SS);
    }
}

// -------- k3: fold BN stats --------
__global__ void k3_bn(const float* __restrict__ gamma, const float* __restrict__ beta)
{
    int c = threadIdx.x;
    const float cnt = (float)((size_t)Nb * Lt * Vv);
    float mean = g_sum[c] / cnt;
    float var  = g_sumsq[c] / cnt - mean * mean;
    float sc   = gamma[c] * rsqrtf(var + BN_EPS);
    g_scale[c] = sc;
    g_shift[c] = beta[c] - mean * sc;
}

// -------- k4: toeplitz recompute + BN + relu + residual + relu --------
__global__ __launch_bounds__(256)
void k4_out(const float* __restrict__ x, float* __restrict__ out)
{
    __shared__ float zs[(LCH + 8) * Vv];
    const int lc = blockIdx.x, c = blockIdx.y, n = blockIdx.z;
    const int l0 = lc * LCH;

    const float* zr = g_z + ((size_t)n * Cout + c) * ((size_t)Lt * Vv);
    for (int i = threadIdx.x; i < (LCH + 8) * Vv; i += 256) {
        int l = l0 - 8 + i / Vv;
        zs[i] = (l >= 0) ? zr[(size_t)l * Vv + (i % Vv)] : 0.f;
    }
    __syncthreads();

    const int l = threadIdx.x;
    const float sc = g_scale[c], sh = g_shift[c];
    const size_t base = ((size_t)(n * Cout + c) * Lt + (l0 + l)) * Vv;
    const float* xr = x + base;
    float* orow = out + base;
    #pragma unroll
    for (int w = 0; w < Vv; ++w) {
        float a = zs[l * Vv + w];
        #pragma unroll
        for (int t = 1; t < 9; ++t) a += zs[(l + t) * Vv + w];
        orow[w] = fmaxf(fmaxf(a * sc + sh, 0.f) + xr[w], 0.f);
    }
}

// ---------------------------------------------------------------------------
extern "C" void kernel_launch(void* const* d_in, const int* in_sizes, int n_in,
                              void* d_out, int out_size)
{
    (void)in_sizes; (void)n_in; (void)out_size;
    const float* x     = (const float*)d_in[0];
    const float* A     = (const float*)d_in[1];
    const float* EI    = (const float*)d_in[2];
    const float* W     = (const float*)d_in[3];
    const float* gamma = (const float*)d_in[4];
    const float* beta  = (const float*)d_in[5];
    float* out = (float*)d_out;

    cudaFuncSetAttribute(k1_gemm, cudaFuncAttributeMaxDynamicSharedMemorySize, SMEM_K1);

    k0_prep<<<1, 128>>>();
    kdummy<<<1, 32>>>();     // shifts ncu's sampled launch slot onto k1/k2
    k1_gemm<<<dim3(Lt / TL, Nb), 512, SMEM_K1>>>(x, A, EI, W);
    k2_stats<<<dim3(Lt / LCH, Cout, Nb), 256>>>();
    k3_bn<<<1, Cout>>>(gamma, beta);
    k4_out<<<dim3(Lt / LCH, Cout, Nb), 256>>>(x, out);
}

// round 5
// speedup vs baseline: 2.7438x; 1.2990x over previous
#include <cuda_runtime.h>
#include <cstdint>

// ===========================================================================
// STGCN block via warp-level tf32 mma.sync:
//   per p:  Y_p = W_p @ X   (m16n8k8 tf32; W double-buffered via cp.async)
//           z  += Y_p @ Aw_p  (C-frag -> A-frag shuffles, streamed per kf/mi
//                              to keep live registers < 128: no spills)
//   k2: BN stats of toeplitz(z) via per-w sliding window
//   k4: sliding-window toeplitz -> smem -> flat coalesced BN/relu/res/relu
// ===========================================================================

namespace {
constexpr int Nb = 8, Cin = 128, Cout = 128, Lt = 2048, Vv = 25, Pp = 3;
constexpr float BN_EPS = 1e-5f;

constexpr int TL   = 4;            // l per CTA in k1
constexpr int XSTR = 136;
constexpr int WSTR = 136;
constexpr int ASTR = 36;

constexpr int X_OFF   = 0;                              // floats
constexpr int W0_OFF  = X_OFF + 128 * XSTR;             // 17408
constexpr int W1_OFF  = W0_OFF + Cout * WSTR;           // 34816
constexpr int AW_OFF  = W1_OFF + Cout * WSTR;           // 52224
constexpr int SM_FLT  = AW_OFF + Pp * 32 * ASTR;        // 55680
constexpr int SMEM_K1 = SM_FLT * 4;                     // 222720 B

constexpr size_t ZSIZE = (size_t)Nb * Cout * Lt * Vv;
constexpr int LCH  = 256;                    // l per CTA in k2/k4
constexpr int HALO = 8 * Vv;                 // 200 floats
constexpr int ZROW = (LCH + 8) * Vv;         // 6600 floats
}

__device__ float g_z[ZSIZE];
__device__ float g_sum[Cout], g_sumsq[Cout], g_scale[Cout], g_shift[Cout];

// -------------------- helpers --------------------
__device__ __forceinline__ uint32_t f2tf32(float x) {
    uint32_t u;
    asm("cvt.rna.tf32.f32 %0, %1;" : "=r"(u) : "f"(x));
    return u;
}
__device__ __forceinline__ uint32_t smem_u32(const void* p) {
    uint32_t a;
    asm("{ .reg .u64 t; cvta.to.shared.u64 t, %1; cvt.u32.u64 %0, t; }" : "=r"(a) : "l"(p));
    return a;
}
__device__ __forceinline__ void mma_tf32(float* d, const uint32_t* a, const uint32_t* b) {
    asm volatile("mma.sync.aligned.m16n8k8.row.col.f32.tf32.tf32.f32 "
        "{%0,%1,%2,%3}, {%4,%5,%6,%7}, {%8,%9}, {%0,%1,%2,%3};"
        : "+f"(d[0]), "+f"(d[1]), "+f"(d[2]), "+f"(d[3])
        : "r"(a[0]), "r"(a[1]), "r"(a[2]), "r"(a[3]), "r"(b[0]), "r"(b[1]));
}
__device__ __forceinline__ int kperm(int k) {
    return (k & ~7) + ((k & 3) << 1) + ((k >> 2) & 1);
}
#define CP_COMMIT() asm volatile("cp.async.commit_group;" ::: "memory")
#define CP_WAIT(n)  asm volatile("cp.async.wait_group %0;" :: "n"(n) : "memory")

__device__ __forceinline__ void cp_w(uint32_t wb, const float* __restrict__ wp, int tid) {
    for (int i = tid; i < Cout * Cin; i += 512) {
        int c = i >> 7, cin = i & 127;
        uint32_t dst = wb + (uint32_t)(c * WSTR + kperm(cin)) * 4u;
        asm volatile("cp.async.ca.shared.global [%0], [%1], 4;"
                     :: "r"(dst), "l"(wp + i) : "memory");
    }
}

__global__ void k0_prep() {
    int t = threadIdx.x;
    if (t < Cout) { g_sum[t] = 0.f; g_sumsq[t] = 0.f; }
}
__global__ void kdummy() {}

// -------- k1: fused conv-GEMM + graph mix --------
// grid (Lt/TL=512, Nb), 512 threads (16 warps: 4 m-groups x 4 l's)
__global__ __launch_bounds__(512, 1)
void k1_gemm(const float* __restrict__ x, const float* __restrict__ A,
             const float* __restrict__ EI, const float* __restrict__ W)
{
    extern __shared__ float sm[];
    uint32_t* Xu  = (uint32_t*)(sm + X_OFF);
    uint32_t* AWu = (uint32_t*)(sm + AW_OFF);

    const int tid  = threadIdx.x;
    const int wid  = tid >> 5;
    const int lane = tid & 31;
    const int n    = blockIdx.y;
    const int l0   = blockIdx.x * TL;

    const int wm = wid >> 2, wl = wid & 3;
    const int m0 = wm * 32,  n0 = wl * 32;
    const int r  = lane >> 2, q = lane & 3;

    const uint32_t smb = smem_u32(sm);
    const uint32_t wb0 = smb + W0_OFF * 4u;
    const uint32_t wb1 = smb + W1_OFF * 4u;

    cp_w(wb0, W, tid);              CP_COMMIT();
    cp_w(wb1, W + Cout * Cin, tid); CP_COMMIT();

    {
        const float* xb = x + (size_t)n * Cin * (Lt * Vv) + (size_t)l0 * Vv;
        for (int i = tid; i < Cin * TL * Vv; i += 512) {
            int cin = i / (TL * Vv);
            int j   = i - cin * (TL * Vv);
            int l   = j / Vv, v = j - l * Vv;
            Xu[(l * 32 + v) * XSTR + kperm(cin)] = f2tf32(xb[(size_t)cin * (Lt * Vv) + j]);
        }
        for (int i = tid; i < TL * 7 * XSTR; i += 512) {
            int l = i / (7 * XSTR), rem = i - l * (7 * XSTR);
            int v = 25 + rem / XSTR, wd = rem % XSTR;
            Xu[(l * 32 + v) * XSTR + wd] = 0u;
        }
        for (int i = tid; i < Pp * 32 * 32; i += 512) {
            int p = i >> 10, rem = i & 1023;
            int w = rem >> 5, v = rem & 31;
            float val = (v < Vv && w < Vv) ? A[p * Vv * Vv + v * Vv + w] * EI[v * Vv + w] : 0.f;
            AWu[p * 32 * ASTR + w * ASTR + kperm(v)] = f2tf32(val);
        }
    }
    CP_WAIT(1);
    __syncthreads();

    const int sidx0 = (lane & ~3) + (q >> 1);
    const int sidx1 = sidx0 + 2;
    const bool odd  = (q & 1);

    float zacc[2][4][4];
    #pragma unroll
    for (int mi = 0; mi < 2; ++mi)
        #pragma unroll
        for (int nj = 0; nj < 4; ++nj)
            #pragma unroll
            for (int i = 0; i < 4; ++i) zacc[mi][nj][i] = 0.f;

    #pragma unroll
    for (int p = 0; p < Pp; ++p) {
        const uint32_t* Wu = (const uint32_t*)(sm + ((p & 1) ? W1_OFF : W0_OFF));

        float yacc[2][4][4];
        #pragma unroll
        for (int mi = 0; mi < 2; ++mi)
            #pragma unroll
            for (int ni = 0; ni < 4; ++ni)
                #pragma unroll
                for (int i = 0; i < 4; ++i) yacc[mi][ni][i] = 0.f;

        #pragma unroll
        for (int kk = 0; kk < 16; ++kk) {
            const int k0 = kk * 8;
            uint32_t af[2][4];
            #pragma unroll
            for (int mi = 0; mi < 2; ++mi) {
                const uint32_t* w0 = Wu + (m0 + 16 * mi + r) * WSTR + k0 + 2 * q;
                uint2 lo = *(const uint2*)w0;
                uint2 hi = *(const uint2*)(w0 + 8 * WSTR);
                af[mi][0] = lo.x; af[mi][1] = hi.x; af[mi][2] = lo.y; af[mi][3] = hi.y;
            }
            uint32_t bf[4][2];
            #pragma unroll
            for (int ni = 0; ni < 4; ++ni) {
                uint2 b = *(const uint2*)(Xu + (n0 + 8 * ni + r) * XSTR + k0 + 2 * q);
                bf[ni][0] = b.x; bf[ni][1] = b.y;
            }
            #pragma unroll
            for (int mi = 0; mi < 2; ++mi)
                #pragma unroll
                for (int ni = 0; ni < 4; ++ni)
                    mma_tf32(yacc[mi][ni], af[mi], bf[ni]);
        }

        // ---- mix, streamed: per kf load B-frags, per mi convert 4 vals + MMA ----
        const uint32_t* awp = AWu + p * 32 * ASTR;
        #pragma unroll
        for (int kf = 0; kf < 4; ++kf) {
            uint32_t bfm[4][2];
            #pragma unroll
            for (int nj = 0; nj < 4; ++nj) {
                uint2 b = *(const uint2*)(awp + (8 * nj + r) * ASTR + 8 * kf + 2 * q);
                bfm[nj][0] = b.x; bfm[nj][1] = b.y;
            }
            #pragma unroll
            for (int mi = 0; mi < 2; ++mi) {
                float c0 = yacc[mi][kf][0], c1 = yacc[mi][kf][1];
                float c2 = yacc[mi][kf][2], c3 = yacc[mi][kf][3];
                float t00 = __shfl_sync(0xffffffffu, c0, sidx0);
                float t01 = __shfl_sync(0xffffffffu, c1, sidx0);
                float t20 = __shfl_sync(0xffffffffu, c0, sidx1);
                float t21 = __shfl_sync(0xffffffffu, c1, sidx1);
                float t10 = __shfl_sync(0xffffffffu, c2, sidx0);
                float t11 = __shfl_sync(0xffffffffu, c3, sidx0);
                float t30 = __shfl_sync(0xffffffffu, c2, sidx1);
                float t31 = __shfl_sync(0xffffffffu, c3, sidx1);
                uint32_t a4[4];
                a4[0] = f2tf32(odd ? t01 : t00);
                a4[1] = f2tf32(odd ? t11 : t10);
                a4[2] = f2tf32(odd ? t21 : t20);
                a4[3] = f2tf32(odd ? t31 : t30);
                #pragma unroll
                for (int nj = 0; nj < 4; ++nj)
                    mma_tf32(zacc[mi][nj], a4, bfm[nj]);
            }
        }

        if (p == 0) {
            __syncthreads();
            cp_w(wb0, W + 2 * Cout * Cin, tid);  CP_COMMIT();
            CP_WAIT(1);
            __syncthreads();
        } else if (p == 1) {
            CP_WAIT(0);
            __syncthreads();
        }
    }

    const int lglob = l0 + wl;
    #pragma unroll
    for (int mi = 0; mi < 2; ++mi) {
        #pragma unroll
        for (int nj = 0; nj < 4; ++nj) {
            int c_lo = m0 + 16 * mi + r;
            int w0c  = 8 * nj + 2 * q;
            float* z0 = g_z + ((size_t)(n * Cout + c_lo) * Lt + lglob) * Vv;
            float* z1 = g_z + ((size_t)(n * Cout + c_lo + 8) * Lt + lglob) * Vv;
            if (w0c < Vv)     { z0[w0c]     = zacc[mi][nj][0]; z1[w0c]     = zacc[mi][nj][2]; }
            if (w0c + 1 < Vv) { z0[w0c + 1] = zacc[mi][nj][1]; z1[w0c + 1] = zacc[mi][nj][3]; }
        }
    }
}

// ---- shared sliding-window toeplitz machinery for k2/k4 ----
// 250 threads active: t = g*Vv + w (g=0..9, w=0..24); each walks 26 l's.
__device__ __forceinline__ void load_zrow(float* zs, const float* zr, int l0, int tid, int nthr)
{
    if (l0 == 0) {
        for (int i = tid; i < HALO; i += nthr) zs[i] = 0.f;
        for (int i = tid; i < LCH * Vv; i += nthr) zs[HALO + i] = zr[i];
    } else {
        const float* src = zr + (size_t)(l0 - 8) * Vv;
        for (int i = tid; i < ZROW; i += nthr) zs[i] = src[i];
    }
}

// -------- k2: BN stats of toeplitz(z) --------
// grid (Lt/LCH, Cout, Nb), 256 threads
__global__ __launch_bounds__(256)
void k2_stats()
{
    __shared__ float zs[ZROW];
    __shared__ float rs[8], rss[8];
    const int lc = blockIdx.x, c = blockIdx.y, n = blockIdx.z;
    const int l0 = lc * LCH;
    const int tid = threadIdx.x;

    const float* zr = g_z + ((size_t)n * Cout + c) * ((size_t)Lt * Vv);
    load_zrow(zs, zr, l0, tid, 256);
    __syncthreads();

    float s = 0.f, ss = 0.f;
    if (tid < 250) {
        const int g = tid / Vv;            // 0..9 (l-chunk)
        const int w = tid - g * Vv;        // 0..24
        const int lbeg = g * 26;           // local l start
        const int lcnt = (g == 9) ? 22 : 26;
        // init window: acc = sum_{d=0..8} zs[(lbeg+d)*25 + w]
        const float* pz = zs + lbeg * Vv + w;
        float acc = 0.f;
        #pragma unroll
        for (int d = 0; d < 9; ++d) acc += pz[d * Vv];
        s = acc; ss = acc * acc;
        const float* padd = pz + 9 * Vv;   // incoming row
        const float* psub = pz;            // outgoing row
        for (int i = 1; i < lcnt; ++i) {
            acc += *padd - *psub;
            padd += Vv; psub += Vv;
            s += acc; ss += acc * acc;
        }
    }
    #pragma unroll
    for (int o = 16; o > 0; o >>= 1) {
        s  += __shfl_down_sync(0xffffffffu, s,  o);
        ss += __shfl_down_sync(0xffffffffu, ss, o);
    }
    if ((tid & 31) == 0) { rs[tid >> 5] = s; rss[tid >> 5] = ss; }
    __syncthreads();
    if (tid == 0) {
        float S = 0.f, SS = 0.f;
        #pragma unroll
        for (int i = 0; i < 8; ++i) { S += rs[i]; SS += rss[i]; }
        atomicAdd(&g_sum[c], S);
        atomicAdd(&g_sumsq[c], SS);
    }
}

// -------- k3: fold BN stats --------
__global__ void k3_bn(const float* __restrict__ gamma, const float* __restrict__ beta)
{
    int c = threadIdx.x;
    const float cnt = (float)((size_t)Nb * Lt * Vv);
    float mean = g_sum[c] / cnt;
    float var  = g_sumsq[c] / cnt - mean * mean;
    float sc   = gamma[c] * rsqrtf(var + BN_EPS);
    g_scale[c] = sc;
    g_shift[c] = beta[c] - mean * sc;
}

// -------- k4: toeplitz -> smem, then flat coalesced epilogue --------
// grid (Lt/LCH, Cout, Nb), 256 threads
__global__ __launch_bounds__(256)
void k4_out(const float* __restrict__ x, float* __restrict__ out)
{
    __shared__ float zs[ZROW];
    __shared__ float as[LCH * Vv];
    const int lc = blockIdx.x, c = blockIdx.y, n = blockIdx.z;
    const int l0 = lc * LCH;
    const int tid = threadIdx.x;

    const float* zr = g_z + ((size_t)n * Cout + c) * ((size_t)Lt * Vv);
    load_zrow(zs, zr, l0, tid, 256);
    __syncthreads();

    if (tid < 250) {
        const int g = tid / Vv;
        const int w = tid - g * Vv;
        const int lbeg = g * 26;
        const int lcnt = (g == 9) ? 22 : 26;
        const float* pz = zs + lbeg * Vv + w;
        float acc = 0.f;
        #pragma unroll
        for (int d = 0; d < 9; ++d) acc += pz[d * Vv];
        float* pa = as + lbeg * Vv + w;
        pa[0] = acc;
        const float* padd = pz + 9 * Vv;
        const float* psub = pz;
        for (int i = 1; i < lcnt; ++i) {
            acc += *padd - *psub;
            padd += Vv; psub += Vv;
            pa[i * Vv] = acc;
        }
    }
    __syncthreads();

    const float sc = g_scale[c], sh = g_shift[c];
    const size_t base = ((size_t)(n * Cout + c) * Lt + l0) * Vv;
    const float* xr = x + base;
    float* orow = out + base;
    for (int i = tid; i < LCH * Vv; i += 256)
        orow[i] = fmaxf(fmaxf(as[i] * sc + sh, 0.f) + xr[i], 0.f);
}

// ---------------------------------------------------------------------------
extern "C" void kernel_launch(void* const* d_in, const int* in_sizes, int n_in,
                              void* d_out, int out_size)
{
    (void)in_sizes; (void)n_in; (void)out_size;
    const float* x     = (const float*)d_in[0];
    const float* A     = (const float*)d_in[1];
    const float* EI    = (const float*)d_in[2];
    const float* W     = (const float*)d_in[3];
    const float* gamma = (const float*)d_in[4];
    const float* beta  = (const float*)d_in[5];
    float* out = (float*)d_out;

    cudaFuncSetAttribute(k1_gemm, cudaFuncAttributeMaxDynamicSharedMemorySize, SMEM_K1);

    k0_prep<<<1, 128>>>();
    kdummy<<<1, 32>>>();
    kdummy<<<1, 32>>>();     // k1 is now the 4th launch -> ncu samples it
    k1_gemm<<<dim3(Lt / TL, Nb), 512, SMEM_K1>>>(x, A, EI, W);
    k2_stats<<<dim3(Lt / LCH, Cout, Nb), 256>>>();
    k3_bn<<<1, Cout>>>(gamma, beta);
    k4_out<<<dim3(Lt / LCH, Cout, Nb), 256>>>(x, out);
}